// round 13
// baseline (speedup 1.0000x reference)
#include <cuda_runtime.h>
#include <cuda_bf16.h>
#include <cstdint>

// Problem constants
#define T_STEPS 1000
#define NCTA_L 96      // persistent grid for LSTM (96 = 3 layers x 32 col-blocks)
#define NTHR_L 512     // 16 warps: 4 K-split groups x 4 batch warps

#define CTA_BAR() asm volatile("bar.sync 0;" ::: "memory")

// ---------------- device scratch (allocation-free) ----------------
__device__ __nv_bfloat16 g_Xh[(size_t)64000 * 256];   // gathered embeddings, bf16 hi
__device__ __nv_bfloat16 g_Xl[(size_t)64000 * 256];   // bf16 lo residual
__device__ __nv_bfloat16 g_Wh[256 * 3072];            // concat Wx top rows, bf16 hi
__device__ __nv_bfloat16 g_Wl[256 * 3072];            // bf16 lo residual
__device__ float g_P[(size_t)64000 * 3072];           // precomputed x@Wx+b, layout [t][col][b]
__device__ uint2 g_B[NCTA_L * 8192];                  // pre-packed recurrent B fragments (6.3MB)
// Full-history h: slot(l,t) = l*1001 + t + 1 (t=-1 is zero slot).
__device__ unsigned g_hb[(size_t)3 * 1001 * 16384];
__device__ unsigned g_qcnt[3 * 4 * 32];               // per-(layer,quarter) counters, 128B apart
__device__ unsigned g_cnt3[3 * 32];                   // per-layer coarse progress (throttle only)

// ---------------- gather + bf16 split ----------------
__global__ void gather_kernel(const int* __restrict__ ids, const float* __restrict__ emb) {
    int r = blockIdx.x;           // r = t*64 + b
    int t = r >> 6, b = r & 63;
    int id = ids[b * 1000 + t];
    float4 v = ((const float4*)(emb + (size_t)id * 256))[threadIdx.x];
    __nv_bfloat16 hx = __float2bfloat16(v.x), hy = __float2bfloat16(v.y);
    __nv_bfloat16 hz = __float2bfloat16(v.z), hw = __float2bfloat16(v.w);
    __nv_bfloat16 lx = __float2bfloat16(v.x - __bfloat162float(hx));
    __nv_bfloat16 ly = __float2bfloat16(v.y - __bfloat162float(hy));
    __nv_bfloat16 lz = __float2bfloat16(v.z - __bfloat162float(hz));
    __nv_bfloat16 lw = __float2bfloat16(v.w - __bfloat162float(hw));
    size_t o = (size_t)r * 256 + threadIdx.x * 4;
    __nv_bfloat162* dh = (__nv_bfloat162*)(g_Xh + o);
    dh[0] = __nv_bfloat162(hx, hy); dh[1] = __nv_bfloat162(hz, hw);
    __nv_bfloat162* dl = (__nv_bfloat162*)(g_Xl + o);
    dl[0] = __nv_bfloat162(lx, ly); dl[1] = __nv_bfloat162(lz, lw);
}

// ---------------- W split ----------------
__global__ void wsplit_kernel(const float* __restrict__ W0x, const float* __restrict__ W1x,
                              const float* __restrict__ W2x) {
    int idx = blockIdx.x * 256 + threadIdx.x;
    int k = idx / 3072, c = idx % 3072;
    int l = c >> 10, cc = c & 1023;
    const float* W = (l == 0) ? W0x : ((l == 1) ? W1x : W2x);
    float v = W[(size_t)k * 1024 + cc];
    __nv_bfloat16 h = __float2bfloat16(v);
    g_Wh[idx] = h;
    g_Wl[idx] = __float2bfloat16(v - __bfloat162float(h));
}

// ---------------- pre-pack recurrent weights + reset counters + zero h(-1) ----------------
__global__ void bprep_kernel(
    const float* __restrict__ W0h, const float* __restrict__ W1h, const float* __restrict__ W2h,
    const float* __restrict__ W1x, const float* __restrict__ W2x)
{
    int gidx = blockIdx.x * 256 + threadIdx.x;
    if (gidx < 96) g_cnt3[gidx] = 0u;
    if (gidx < 3 * 4 * 32) g_qcnt[gidx] = 0u;
    if (gidx < 3 * 16384) {
        int l = gidx / 16384, i = gidx % 16384;
        g_hb[(size_t)l * 1001 * 16384 + i] = 0u;    // slot(l, -1) = zeros
    }

    int cta = gidx >> 13, rem = gidx & 8191;
    int chunk = rem >> 8, split = (rem >> 7) & 1, ni = (rem >> 5) & 3, lane = rem & 31;
    int l = cta / 32, cb = cta % 32;
    int n = lane >> 2, tg = lane & 3;
    int c = ni * 8 + n;
    int oc = (c & 3) * 256 + cb * 8 + (c >> 2);
    int k0 = chunk * 16;

    uint2 out_v = make_uint2(0u, 0u);
    if (!(l == 0 && chunk >= 16)) {
        const float* Whl = (l == 0) ? W0h : ((l == 1) ? W1h : W2h);
        const float* Wxl = (l <= 1) ? W1x : W2x;
        int offs[4] = {2 * tg, 2 * tg + 1, 2 * tg + 8, 2 * tg + 9};
        unsigned short sv[4];
#pragma unroll
        for (int j = 0; j < 4; j++) {
            int k = k0 + offs[j];
            float v = (k < 256) ? Whl[(size_t)k * 1024 + oc] : Wxl[(size_t)k * 1024 + oc];
            __nv_bfloat16 h = __float2bfloat16(v);
            __nv_bfloat16 lo = __float2bfloat16(v - __bfloat162float(h));
            __nv_bfloat16 sel = split ? lo : h;
            sv[j] = __bfloat16_as_ushort(sel);
        }
        out_v.x = (unsigned)sv[0] | ((unsigned)sv[1] << 16);
        out_v.y = (unsigned)sv[2] | ((unsigned)sv[3] << 16);
    }
    g_B[gidx] = out_v;
}

// ---------------- MMA primitive ----------------
__device__ __forceinline__ void mma_bf16(float& d0, float& d1, float& d2, float& d3,
                                         unsigned a0, unsigned a1, unsigned a2, unsigned a3,
                                         unsigned b0, unsigned b1) {
    asm volatile(
        "mma.sync.aligned.m16n8k16.row.col.f32.bf16.bf16.f32 "
        "{%0,%1,%2,%3},{%4,%5,%6,%7},{%8,%9},{%0,%1,%2,%3};"
        : "+f"(d0), "+f"(d1), "+f"(d2), "+f"(d3)
        : "r"(a0), "r"(a1), "r"(a2), "r"(a3), "r"(b0), "r"(b1));
}

#define LDU(arr, elem_idx) (*(const unsigned*)&(arr)[(elem_idx)])

// ---------------- bf16-split MMA GEMM with SMEM double-buffering ----------------
__global__ void __launch_bounds__(256) mma_gemm_kernel(
    const float* __restrict__ b0_, const float* __restrict__ b1_, const float* __restrict__ b2_)
{
    __shared__ __align__(16) __nv_bfloat16 Xh_s[2][128 * 20];
    __shared__ __align__(16) __nv_bfloat16 Xl_s[2][128 * 20];
    __shared__ __align__(16) __nv_bfloat16 Wh_s[2][64 * 20];
    __shared__ __align__(16) __nv_bfloat16 Wl_s[2][64 * 20];

    const int tid = threadIdx.x;
    const int warp = tid >> 5, lane = tid & 31;
    const int wm = (warp >> 1) * 32, wn = (warp & 1) * 32;
    const int rbase = blockIdx.x * 128;
    const int cbase = blockIdx.y * 64;
    const int layer = cbase >> 10;
    const float* bias = (layer == 0) ? b0_ : ((layer == 1) ? b1_ : b2_);
    const int r = lane >> 2, tg = lane & 3;
    const int xrow = tid >> 1, xhalf = tid & 1;

    float acc[2][4][4];
#pragma unroll
    for (int i = 0; i < 2; i++)
#pragma unroll
        for (int j = 0; j < 4; j++)
#pragma unroll
            for (int e = 0; e < 4; e++) acc[i][j][e] = 0.0f;

    uint4 vh, vl;
    __nv_bfloat16 wrh[4], wrl[4];
    auto gload = [&](int k0) {
        vh = *(const uint4*)(g_Xh + (size_t)(rbase + xrow) * 256 + k0 + xhalf * 8);
        vl = *(const uint4*)(g_Xl + (size_t)(rbase + xrow) * 256 + k0 + xhalf * 8);
#pragma unroll
        for (int j = 0; j < 4; j++) {
            int i = tid + j * 256;
            int kk = i >> 6, cc = i & 63;
            wrh[j] = g_Wh[(size_t)(k0 + kk) * 3072 + cbase + cc];
            wrl[j] = g_Wl[(size_t)(k0 + kk) * 3072 + cbase + cc];
        }
    };
    auto sstore = [&](int buf) {
        unsigned* dx = (unsigned*)Xh_s[buf] + xrow * 10 + xhalf * 4;
        dx[0] = vh.x; dx[1] = vh.y; dx[2] = vh.z; dx[3] = vh.w;
        unsigned* dl = (unsigned*)Xl_s[buf] + xrow * 10 + xhalf * 4;
        dl[0] = vl.x; dl[1] = vl.y; dl[2] = vl.z; dl[3] = vl.w;
#pragma unroll
        for (int j = 0; j < 4; j++) {
            int i = tid + j * 256;
            int kk = i >> 6, cc = i & 63;
            Wh_s[buf][cc * 20 + kk] = wrh[j];
            Wl_s[buf][cc * 20 + kk] = wrl[j];
        }
    };

    gload(0);
    sstore(0);
    __syncthreads();

    for (int j16 = 0; j16 < 16; j16++) {
        const int cur = j16 & 1;
        if (j16 < 15) gload((j16 + 1) * 16);

        unsigned ah[2][4], al[2][4];
#pragma unroll
        for (int mi = 0; mi < 2; mi++) {
            int row0 = (wm + mi * 16 + r) * 20;
            int row1 = row0 + 8 * 20;
            ah[mi][0] = LDU(Xh_s[cur], row0 + 2 * tg);
            ah[mi][1] = LDU(Xh_s[cur], row1 + 2 * tg);
            ah[mi][2] = LDU(Xh_s[cur], row0 + 2 * tg + 8);
            ah[mi][3] = LDU(Xh_s[cur], row1 + 2 * tg + 8);
            al[mi][0] = LDU(Xl_s[cur], row0 + 2 * tg);
            al[mi][1] = LDU(Xl_s[cur], row1 + 2 * tg);
            al[mi][2] = LDU(Xl_s[cur], row0 + 2 * tg + 8);
            al[mi][3] = LDU(Xl_s[cur], row1 + 2 * tg + 8);
        }
#pragma unroll
        for (int ni = 0; ni < 4; ni++) {
            int col = (wn + ni * 8 + r) * 20;
            unsigned bh0 = LDU(Wh_s[cur], col + 2 * tg);
            unsigned bh1 = LDU(Wh_s[cur], col + 2 * tg + 8);
            unsigned bl0 = LDU(Wl_s[cur], col + 2 * tg);
            unsigned bl1 = LDU(Wl_s[cur], col + 2 * tg + 8);
#pragma unroll
            for (int mi = 0; mi < 2; mi++) {
                mma_bf16(acc[mi][ni][0], acc[mi][ni][1], acc[mi][ni][2], acc[mi][ni][3],
                         ah[mi][0], ah[mi][1], ah[mi][2], ah[mi][3], bh0, bh1);
                mma_bf16(acc[mi][ni][0], acc[mi][ni][1], acc[mi][ni][2], acc[mi][ni][3],
                         ah[mi][0], ah[mi][1], ah[mi][2], ah[mi][3], bl0, bl1);
                mma_bf16(acc[mi][ni][0], acc[mi][ni][1], acc[mi][ni][2], acc[mi][ni][3],
                         al[mi][0], al[mi][1], al[mi][2], al[mi][3], bh0, bh1);
            }
        }
        if (j16 < 15) sstore(cur ^ 1);
        __syncthreads();
    }

#pragma unroll
    for (int mi = 0; mi < 2; mi++) {
#pragma unroll
        for (int ni = 0; ni < 4; ni++) {
            int gc = cbase + wn + ni * 8 + 2 * tg;
            float bi0 = bias[gc & 1023];
            float bi1 = bias[(gc + 1) & 1023];
            int grow0 = rbase + wm + mi * 16 + r;
            int grow1 = grow0 + 8;
            size_t o0 = ((size_t)(grow0 >> 6) * 3072 + gc) * 64 + (grow0 & 63);
            size_t o1 = ((size_t)(grow1 >> 6) * 3072 + gc) * 64 + (grow1 & 63);
            g_P[o0]      = acc[mi][ni][0] + bi0;
            g_P[o0 + 64] = acc[mi][ni][1] + bi1;
            g_P[o1]      = acc[mi][ni][2] + bi0;
            g_P[o1 + 64] = acc[mi][ni][3] + bi1;
        }
    }
}

// ---------------- recurrent persistent kernel (quarter-counter ring sync) ----------------
__device__ __forceinline__ float sigf(float x) { return 1.0f / (1.0f + __expf(-x)); }
__device__ __forceinline__ float tanhf_fast(float x) {
    float e = __expf(2.0f * x);
    return 1.0f - __fdividef(2.0f, e + 1.0f);
}
__device__ __forceinline__ unsigned ldcg_u32(const void* p) {
    unsigned v;
    asm volatile("ld.global.cg.b32 %0, [%1];" : "=r"(v) : "l"(p));
    return v;
}
__device__ __forceinline__ void spin_until(const unsigned* p, unsigned need) {
    unsigned v;
    int s = 0;
    for (;;) {
        asm volatile("ld.global.acquire.gpu.b32 %0, [%1];" : "=r"(v) : "l"(p));
        if (v >= need) break;
        if (s < 4) { s++; } else { __nanosleep(s < 10 ? 64 : 128); if (s < 10) s++; }
    }
}

// single chunk: local chunk index cl (h address), B-frag index gb
__device__ __forceinline__ void mma_chunk(float (&acc)[4][4], const unsigned* hi,
                                          const uint2* Bsm, int cl, int gb,
                                          int br, int br8, int tg, int lane)
{
    const unsigned* lo = hi + 8192;
    const int k2b = cl * 8;
    unsigned a[8];
    a[0] = ldcg_u32(hi + (k2b + tg) * 64 + br);
    a[1] = ldcg_u32(hi + (k2b + tg) * 64 + br8);
    a[2] = ldcg_u32(hi + (k2b + tg + 4) * 64 + br);
    a[3] = ldcg_u32(hi + (k2b + tg + 4) * 64 + br8);
    a[4] = ldcg_u32(lo + (k2b + tg) * 64 + br);
    a[5] = ldcg_u32(lo + (k2b + tg) * 64 + br8);
    a[6] = ldcg_u32(lo + (k2b + tg + 4) * 64 + br);
    a[7] = ldcg_u32(lo + (k2b + tg + 4) * 64 + br8);
    const uint2* bsc = Bsm + gb * 256;
#pragma unroll
    for (int ni = 0; ni < 4; ni++) {
        uint2 bh = bsc[ni * 32 + lane];
        uint2 bl = bsc[128 + ni * 32 + lane];
        mma_bf16(acc[ni][0], acc[ni][1], acc[ni][2], acc[ni][3],
                 a[0], a[1], a[2], a[3], bh.x, bh.y);
        mma_bf16(acc[ni][0], acc[ni][1], acc[ni][2], acc[ni][3],
                 a[0], a[1], a[2], a[3], bl.x, bl.y);
        mma_bf16(acc[ni][0], acc[ni][1], acc[ni][2], acc[ni][3],
                 a[4], a[5], a[6], a[7], bh.x, bh.y);
    }
}

// two consecutive chunks (loads for both issued before MMAs)
__device__ __forceinline__ void mma_chunk2(float (&acc)[4][4], const unsigned* hi,
                                           const uint2* Bsm, int cl, int gb,
                                           int br, int br8, int tg, int lane)
{
    const unsigned* lo = hi + 8192;
    unsigned a[2][8];
#pragma unroll
    for (int j = 0; j < 2; j++) {
        const int k2b = (cl + j) * 8;
        a[j][0] = ldcg_u32(hi + (k2b + tg) * 64 + br);
        a[j][1] = ldcg_u32(hi + (k2b + tg) * 64 + br8);
        a[j][2] = ldcg_u32(hi + (k2b + tg + 4) * 64 + br);
        a[j][3] = ldcg_u32(hi + (k2b + tg + 4) * 64 + br8);
        a[j][4] = ldcg_u32(lo + (k2b + tg) * 64 + br);
        a[j][5] = ldcg_u32(lo + (k2b + tg) * 64 + br8);
        a[j][6] = ldcg_u32(lo + (k2b + tg + 4) * 64 + br);
        a[j][7] = ldcg_u32(lo + (k2b + tg + 4) * 64 + br8);
    }
#pragma unroll
    for (int j = 0; j < 2; j++) {
        const uint2* bsc = Bsm + (gb + j) * 256;
#pragma unroll
        for (int ni = 0; ni < 4; ni++) {
            uint2 bh = bsc[ni * 32 + lane];
            uint2 bl = bsc[128 + ni * 32 + lane];
            mma_bf16(acc[ni][0], acc[ni][1], acc[ni][2], acc[ni][3],
                     a[j][0], a[j][1], a[j][2], a[j][3], bh.x, bh.y);
            mma_bf16(acc[ni][0], acc[ni][1], acc[ni][2], acc[ni][3],
                     a[j][0], a[j][1], a[j][2], a[j][3], bl.x, bl.y);
            mma_bf16(acc[ni][0], acc[ni][1], acc[ni][2], acc[ni][3],
                     a[j][4], a[j][5], a[j][6], a[j][7], bh.x, bh.y);
        }
    }
}

__global__ void __launch_bounds__(NTHR_L) lstm_kernel(float* __restrict__ out)
{
    extern __shared__ uint2 Bs[];             // 64 KB B-frags + 32 KB parity-buffered red
    float* redbuf = (float*)(Bs + 8192);      // [par][grp][wq][lane][16]

    const int tid = threadIdx.x;
    const int cta = blockIdx.x;
    const int w = tid >> 5, lane = tid & 31;
    const int wq = w & 3, grp = w >> 2;       // batch-warp index, K-split group (0..3)
    const int r = lane >> 2, tg = lane & 3;
    const int l = cta / 32, cb = cta % 32;
    const int br  = wq * 16 + r;
    const int br8 = br + 8;

    {
        const uint4* src = (const uint4*)g_B + (size_t)cta * 4096;
        uint4* dst = (uint4*)Bs;
        for (int i = tid; i < 4096; i += NTHR_L) dst[i] = src[i];
    }
    __syncthreads();

    float cst[2] = {0.0f, 0.0f};

    unsigned* const myCnt  = g_cnt3 + l * 32;
    const unsigned* const aboCnt = g_cnt3 + (l + 1) * 32;
    unsigned* const qOwnBase = g_qcnt + (l * 4) * 32;          // own-layer quarter counters
    const unsigned* const qBelBase = g_qcnt + ((l - 1) * 4) * 32;
    const int myq = cb >> 3;                                    // quarter this CTA produces
    const int q0 = (myq + grp) & 3;                             // staggered ring start

    for (int t = 0; t < T_STEPS; t++) {
        const unsigned* ownHi = g_hb + (size_t)(l * 1001 + t) * 16384;   // h_l(t-1)
        float* red = redbuf + (t & 1) * (4 * 4 * 32 * 16);

        // coarse run-ahead throttle (warp 0 only; CTA_BAR propagates the stall)
        if (w == 0 && l < 2 && t >= 64 && (t & 7) == 0) {
            if (lane == 0) spin_until(aboCnt, 32u * ((unsigned)(t - 64) & ~7u));
            __syncwarp();
        }

        float acc[4][4];
#pragma unroll
        for (int ni = 0; ni < 4; ni++)
#pragma unroll
            for (int e = 0; e < 4; e++) acc[ni][e] = 0.0f;

        if (grp < 2) {
            const int nbase = grp * 2;
            // P prefetch for this half (before any waits)
            float pv[2][4];
            {
                const float* basep = g_P + (size_t)(t * 3 + l) * 1024 * 64;
#pragma unroll
                for (int jj = 0; jj < 2; jj++) {
                    int ni = nbase + jj;
                    int ug = cb * 8 + 2 * ni + (tg >> 1);
                    int oc0 = (tg & 1) * 512 + ug;
                    int oc1 = oc0 + 256;
                    pv[jj][0] = __ldcs(basep + (size_t)oc0 * 64 + br);
                    pv[jj][1] = __ldcs(basep + (size_t)oc1 * 64 + br);
                    pv[jj][2] = __ldcs(basep + (size_t)oc0 * 64 + br8);
                    pv[jj][3] = __ldcs(basep + (size_t)oc1 * 64 + br8);
                }
            }
            // own-h ring: 4 quarters, 1 chunk each (chunk 4q+grp)
#pragma unroll
            for (int qi = 0; qi < 4; qi++) {
                int q = (q0 + qi) & 3;
                if (t > 0) spin_until(qOwnBase + q * 32, 64u * (unsigned)t);
                mma_chunk(acc, ownHi, Bs, 4 * q + grp, 4 * q + grp, br, br8, tg, lane);
            }
#pragma unroll
            for (int ni = 0; ni < 4; ni++) {
                float* rd = red + ((grp * 4 + wq) * 32 + lane) * 16 + ni * 4;
                rd[0] = acc[ni][0]; rd[1] = acc[ni][1]; rd[2] = acc[ni][2]; rd[3] = acc[ni][3];
            }
            CTA_BAR();

            // epilogue for this half
            unsigned* whh = g_hb + (size_t)(l * 1001 + t + 1) * 16384;
            unsigned* wll = whh + 8192;
#pragma unroll
            for (int jj = 0; jj < 2; jj++) {
                int ni = nbase + jj;
                float v0 = acc[ni][0], v1 = acc[ni][1], v2 = acc[ni][2], v3 = acc[ni][3];
#pragma unroll
                for (int g = 0; g < 4; g++) {
                    if (g == grp) continue;
                    const float* rd = red + ((g * 4 + wq) * 32 + lane) * 16 + ni * 4;
                    v0 += rd[0]; v1 += rd[1]; v2 += rd[2]; v3 += rd[3];
                }
                v0 += pv[jj][0]; v1 += pv[jj][1]; v2 += pv[jj][2]; v3 += pv[jj][3];
                float s0 = __shfl_xor_sync(0xffffffffu, (tg & 1) ? v0 : v2, 1);
                float s1 = __shfl_xor_sync(0xffffffffu, (tg & 1) ? v1 : v3, 1);
                float gi_, gj_, gf_, go_;
                int brow;
                if (!(tg & 1)) { gi_ = v0; gj_ = v1; gf_ = s0; go_ = s1; brow = br; }
                else           { gi_ = s0; gj_ = s1; gf_ = v2; go_ = v3; brow = br8; }
                float cn = sigf(gf_) * cst[jj] + sigf(gi_) * tanhf_fast(gj_);
                cst[jj] = cn;
                float h = sigf(go_) * tanhf_fast(cn);
                unsigned hh16 = (unsigned)__bfloat16_as_ushort(__float2bfloat16(h));
                float hhf = __bfloat162float(__float2bfloat16(h));
                unsigned hl16 = (unsigned)__bfloat16_as_ushort(__float2bfloat16(h - hhf));
                unsigned ph = __shfl_xor_sync(0xffffffffu, hh16, 2);
                unsigned pl = __shfl_xor_sync(0xffffffffu, hl16, 2);
                if (tg < 2) {
                    int k2 = cb * 4 + ni;
                    whh[k2 * 64 + brow] = hh16 | (ph << 16);
                    wll[k2 * 64 + brow] = hl16 | (pl << 16);
                }
                if (t == T_STEPS - 1) {
                    int ug = cb * 8 + 2 * ni + (tg >> 1);
                    out[brow * 1536 + l * 512 + ug] = cn;
                    out[brow * 1536 + l * 512 + 256 + ug] = h;
                }
            }
            // warp-autonomous release: one arrival per epilogue warp on own quarter
            __threadfence();
            if (lane == 0) atomicAdd(qOwnBase + myq * 32, 1u);
            // coarse progress for the throttle (off critical path)
            if (w == 0 && lane == 0 && (t & 7) == 7) atomicAdd(myCnt, 8u);
        } else {
            // grps 2,3: below-h ring first (producer ahead; per-quarter gated), then own-h ring
            if (l > 0) {
                const unsigned* belHi = g_hb + (size_t)((l - 1) * 1001 + t + 1) * 16384;
#pragma unroll
                for (int qi = 0; qi < 4; qi++) {
                    int q = (q0 + qi) & 3;
                    spin_until(qBelBase + q * 32, 64u * (unsigned)(t + 1));
                    int c0 = 4 * q + 2 * (grp - 2);
                    mma_chunk2(acc, belHi, Bs, c0, 16 + c0, br, br8, tg, lane);
                }
            }
#pragma unroll
            for (int qi = 0; qi < 4; qi++) {
                int q = (q0 + qi) & 3;
                if (t > 0) spin_until(qOwnBase + q * 32, 64u * (unsigned)t);
                mma_chunk(acc, ownHi, Bs, 4 * q + grp, 4 * q + grp, br, br8, tg, lane);
            }
#pragma unroll
            for (int ni = 0; ni < 4; ni++) {
                float* rd = red + ((grp * 4 + wq) * 32 + lane) * 16 + ni * 4;
                rd[0] = acc[ni][0]; rd[1] = acc[ni][1]; rd[2] = acc[ni][2]; rd[3] = acc[ni][3];
            }
            CTA_BAR();
        }
    }
}

// ---------------- launch ----------------
extern "C" void kernel_launch(void* const* d_in, const int* in_sizes, int n_in,
                              void* d_out, int out_size) {
    const int*   ids = (const int*)d_in[0];
    const float* emb = (const float*)d_in[1];
    const float* W0x = (const float*)d_in[2];
    const float* W0h = (const float*)d_in[3];
    const float* b0  = (const float*)d_in[4];
    const float* W1x = (const float*)d_in[5];
    const float* W1h = (const float*)d_in[6];
    const float* b1  = (const float*)d_in[7];
    const float* W2x = (const float*)d_in[8];
    const float* W2h = (const float*)d_in[9];
    const float* b2  = (const float*)d_in[10];
    float* out = (float*)d_out;

    static bool attr_set = false;
    if (!attr_set) {
        cudaFuncSetAttribute(lstm_kernel, cudaFuncAttributeMaxDynamicSharedMemorySize, 131072);
        attr_set = true;
    }

    gather_kernel<<<64000, 64>>>(ids, emb);
    wsplit_kernel<<<3072, 256>>>(W0x, W1x, W2x);
    bprep_kernel<<<3072, 256>>>(W0h, W1h, W2h, W1x, W2x);
    dim3 gg(500, 48);
    mma_gemm_kernel<<<gg, 256>>>(b0, b1, b2);
    lstm_kernel<<<NCTA_L, NTHR_L, 131072>>>(out);
}

// round 14
// speedup vs baseline: 1.3294x; 1.3294x over previous
#include <cuda_runtime.h>
#include <cuda_bf16.h>
#include <cstdint>

// Problem constants
#define T_STEPS 1000
#define NCTA_L 96      // persistent grid for LSTM (96 = 3 layers x 32 col-blocks)
#define NTHR_L 512     // 16 warps: 4 K-split groups x 4 batch-quadrant warps

#define NBAR(id) asm volatile("bar.sync %0, %1;" :: "r"(id), "r"(128) : "memory")

// ---------------- device scratch (allocation-free) ----------------
__device__ __nv_bfloat16 g_Xh[(size_t)64000 * 256];   // gathered embeddings, bf16 hi
__device__ __nv_bfloat16 g_Xl[(size_t)64000 * 256];   // bf16 lo residual
__device__ __nv_bfloat16 g_Wh[256 * 3072];            // concat Wx top rows, bf16 hi
__device__ __nv_bfloat16 g_Wl[256 * 3072];            // bf16 lo residual
__device__ float g_P[(size_t)64000 * 3072];           // precomputed x@Wx+b, layout [t][col][b]
__device__ uint2 g_B[NCTA_L * 8192];                  // pre-packed recurrent B fragments (6.3MB)
// Full-history h: slot(l,t) = l*1001 + t + 1 (t=-1 is zero slot).
__device__ unsigned g_hb[(size_t)3 * 1001 * 16384];
__device__ unsigned g_qw[3 * 4 * 32];                 // per-(layer, batch-quadrant) counters

// ---------------- gather + bf16 split ----------------
__global__ void gather_kernel(const int* __restrict__ ids, const float* __restrict__ emb) {
    int r = blockIdx.x;           // r = t*64 + b
    int t = r >> 6, b = r & 63;
    int id = ids[b * 1000 + t];
    float4 v = ((const float4*)(emb + (size_t)id * 256))[threadIdx.x];
    __nv_bfloat16 hx = __float2bfloat16(v.x), hy = __float2bfloat16(v.y);
    __nv_bfloat16 hz = __float2bfloat16(v.z), hw = __float2bfloat16(v.w);
    __nv_bfloat16 lx = __float2bfloat16(v.x - __bfloat162float(hx));
    __nv_bfloat16 ly = __float2bfloat16(v.y - __bfloat162float(hy));
    __nv_bfloat16 lz = __float2bfloat16(v.z - __bfloat162float(hz));
    __nv_bfloat16 lw = __float2bfloat16(v.w - __bfloat162float(hw));
    size_t o = (size_t)r * 256 + threadIdx.x * 4;
    __nv_bfloat162* dh = (__nv_bfloat162*)(g_Xh + o);
    dh[0] = __nv_bfloat162(hx, hy); dh[1] = __nv_bfloat162(hz, hw);
    __nv_bfloat162* dl = (__nv_bfloat162*)(g_Xl + o);
    dl[0] = __nv_bfloat162(lx, ly); dl[1] = __nv_bfloat162(lz, lw);
}

// ---------------- W split ----------------
__global__ void wsplit_kernel(const float* __restrict__ W0x, const float* __restrict__ W1x,
                              const float* __restrict__ W2x) {
    int idx = blockIdx.x * 256 + threadIdx.x;
    int k = idx / 3072, c = idx % 3072;
    int l = c >> 10, cc = c & 1023;
    const float* W = (l == 0) ? W0x : ((l == 1) ? W1x : W2x);
    float v = W[(size_t)k * 1024 + cc];
    __nv_bfloat16 h = __float2bfloat16(v);
    g_Wh[idx] = h;
    g_Wl[idx] = __float2bfloat16(v - __bfloat162float(h));
}

// ---------------- pre-pack recurrent weights + reset counters + zero h(-1) ----------------
__global__ void bprep_kernel(
    const float* __restrict__ W0h, const float* __restrict__ W1h, const float* __restrict__ W2h,
    const float* __restrict__ W1x, const float* __restrict__ W2x)
{
    int gidx = blockIdx.x * 256 + threadIdx.x;
    if (gidx < 3 * 4 * 32) g_qw[gidx] = 0u;
    if (gidx < 3 * 16384) {
        int l = gidx / 16384, i = gidx % 16384;
        g_hb[(size_t)l * 1001 * 16384 + i] = 0u;    // slot(l, -1) = zeros
    }

    int cta = gidx >> 13, rem = gidx & 8191;
    int chunk = rem >> 8, split = (rem >> 7) & 1, ni = (rem >> 5) & 3, lane = rem & 31;
    int l = cta / 32, cb = cta % 32;
    int n = lane >> 2, tg = lane & 3;
    int c = ni * 8 + n;
    int oc = (c & 3) * 256 + cb * 8 + (c >> 2);
    int k0 = chunk * 16;

    uint2 out_v = make_uint2(0u, 0u);
    if (!(l == 0 && chunk >= 16)) {
        const float* Whl = (l == 0) ? W0h : ((l == 1) ? W1h : W2h);
        const float* Wxl = (l <= 1) ? W1x : W2x;
        int offs[4] = {2 * tg, 2 * tg + 1, 2 * tg + 8, 2 * tg + 9};
        unsigned short sv[4];
#pragma unroll
        for (int j = 0; j < 4; j++) {
            int k = k0 + offs[j];
            float v = (k < 256) ? Whl[(size_t)k * 1024 + oc] : Wxl[(size_t)k * 1024 + oc];
            __nv_bfloat16 h = __float2bfloat16(v);
            __nv_bfloat16 lo = __float2bfloat16(v - __bfloat162float(h));
            __nv_bfloat16 sel = split ? lo : h;
            sv[j] = __bfloat16_as_ushort(sel);
        }
        out_v.x = (unsigned)sv[0] | ((unsigned)sv[1] << 16);
        out_v.y = (unsigned)sv[2] | ((unsigned)sv[3] << 16);
    }
    g_B[gidx] = out_v;
}

// ---------------- MMA primitive ----------------
__device__ __forceinline__ void mma_bf16(float& d0, float& d1, float& d2, float& d3,
                                         unsigned a0, unsigned a1, unsigned a2, unsigned a3,
                                         unsigned b0, unsigned b1) {
    asm volatile(
        "mma.sync.aligned.m16n8k16.row.col.f32.bf16.bf16.f32 "
        "{%0,%1,%2,%3},{%4,%5,%6,%7},{%8,%9},{%0,%1,%2,%3};"
        : "+f"(d0), "+f"(d1), "+f"(d2), "+f"(d3)
        : "r"(a0), "r"(a1), "r"(a2), "r"(a3), "r"(b0), "r"(b1));
}

#define LDU(arr, elem_idx) (*(const unsigned*)&(arr)[(elem_idx)])

// ---------------- bf16-split MMA GEMM: P = X @ W + bias (R10-proven version) ----------------
__global__ void __launch_bounds__(256) mma_gemm_kernel(
    const float* __restrict__ b0_, const float* __restrict__ b1_, const float* __restrict__ b2_)
{
    __shared__ __align__(16) __nv_bfloat16 Xh_s[128 * 20];
    __shared__ __align__(16) __nv_bfloat16 Xl_s[128 * 20];
    __shared__ __align__(16) __nv_bfloat16 Wh_s[64 * 20];
    __shared__ __align__(16) __nv_bfloat16 Wl_s[64 * 20];

    const int tid = threadIdx.x;
    const int warp = tid >> 5, lane = tid & 31;
    const int wm = (warp >> 1) * 32, wn = (warp & 1) * 32;
    const int rbase = blockIdx.x * 128;
    const int cbase = blockIdx.y * 64;
    const int layer = cbase >> 10;
    const float* bias = (layer == 0) ? b0_ : ((layer == 1) ? b1_ : b2_);
    const int r = lane >> 2, tg = lane & 3;
    const int xrow = tid >> 1, xhalf = tid & 1;

    float acc[2][4][4];
#pragma unroll
    for (int i = 0; i < 2; i++)
#pragma unroll
        for (int j = 0; j < 4; j++)
#pragma unroll
            for (int e = 0; e < 4; e++) acc[i][j][e] = 0.0f;

    for (int k0 = 0; k0 < 256; k0 += 16) {
        uint4 vh = *(const uint4*)(g_Xh + (size_t)(rbase + xrow) * 256 + k0 + xhalf * 8);
        uint4 vl = *(const uint4*)(g_Xl + (size_t)(rbase + xrow) * 256 + k0 + xhalf * 8);
        __nv_bfloat16 wrh[4], wrl[4];
#pragma unroll
        for (int j = 0; j < 4; j++) {
            int i = tid + j * 256;
            int kk = i >> 6, cc = i & 63;
            wrh[j] = g_Wh[(size_t)(k0 + kk) * 3072 + cbase + cc];
            wrl[j] = g_Wl[(size_t)(k0 + kk) * 3072 + cbase + cc];
        }
        __syncthreads();
        {
            unsigned* dx = (unsigned*)Xh_s + xrow * 10 + xhalf * 4;
            dx[0] = vh.x; dx[1] = vh.y; dx[2] = vh.z; dx[3] = vh.w;
            unsigned* dl = (unsigned*)Xl_s + xrow * 10 + xhalf * 4;
            dl[0] = vl.x; dl[1] = vl.y; dl[2] = vl.z; dl[3] = vl.w;
        }
#pragma unroll
        for (int j = 0; j < 4; j++) {
            int i = tid + j * 256;
            int kk = i >> 6, cc = i & 63;
            Wh_s[cc * 20 + kk] = wrh[j];
            Wl_s[cc * 20 + kk] = wrl[j];
        }
        __syncthreads();

        unsigned ah[2][4], al[2][4];
#pragma unroll
        for (int mi = 0; mi < 2; mi++) {
            int row0 = (wm + mi * 16 + r) * 20;
            int row1 = row0 + 8 * 20;
            ah[mi][0] = LDU(Xh_s, row0 + 2 * tg);
            ah[mi][1] = LDU(Xh_s, row1 + 2 * tg);
            ah[mi][2] = LDU(Xh_s, row0 + 2 * tg + 8);
            ah[mi][3] = LDU(Xh_s, row1 + 2 * tg + 8);
            al[mi][0] = LDU(Xl_s, row0 + 2 * tg);
            al[mi][1] = LDU(Xl_s, row1 + 2 * tg);
            al[mi][2] = LDU(Xl_s, row0 + 2 * tg + 8);
            al[mi][3] = LDU(Xl_s, row1 + 2 * tg + 8);
        }
#pragma unroll
        for (int ni = 0; ni < 4; ni++) {
            int col = (wn + ni * 8 + r) * 20;
            unsigned bh0 = LDU(Wh_s, col + 2 * tg);
            unsigned bh1 = LDU(Wh_s, col + 2 * tg + 8);
            unsigned bl0 = LDU(Wl_s, col + 2 * tg);
            unsigned bl1 = LDU(Wl_s, col + 2 * tg + 8);
#pragma unroll
            for (int mi = 0; mi < 2; mi++) {
                mma_bf16(acc[mi][ni][0], acc[mi][ni][1], acc[mi][ni][2], acc[mi][ni][3],
                         ah[mi][0], ah[mi][1], ah[mi][2], ah[mi][3], bh0, bh1);
                mma_bf16(acc[mi][ni][0], acc[mi][ni][1], acc[mi][ni][2], acc[mi][ni][3],
                         ah[mi][0], ah[mi][1], ah[mi][2], ah[mi][3], bl0, bl1);
                mma_bf16(acc[mi][ni][0], acc[mi][ni][1], acc[mi][ni][2], acc[mi][ni][3],
                         al[mi][0], al[mi][1], al[mi][2], al[mi][3], bh0, bh1);
            }
        }
    }

#pragma unroll
    for (int mi = 0; mi < 2; mi++) {
#pragma unroll
        for (int ni = 0; ni < 4; ni++) {
            int gc = cbase + wn + ni * 8 + 2 * tg;
            float bi0 = bias[gc & 1023];
            float bi1 = bias[(gc + 1) & 1023];
            int grow0 = rbase + wm + mi * 16 + r;
            int grow1 = grow0 + 8;
            size_t o0 = ((size_t)(grow0 >> 6) * 3072 + gc) * 64 + (grow0 & 63);
            size_t o1 = ((size_t)(grow1 >> 6) * 3072 + gc) * 64 + (grow1 & 63);
            g_P[o0]      = acc[mi][ni][0] + bi0;
            g_P[o0 + 64] = acc[mi][ni][1] + bi1;
            g_P[o1]      = acc[mi][ni][2] + bi0;
            g_P[o1 + 64] = acc[mi][ni][3] + bi1;
        }
    }
}

// ---------------- recurrent persistent kernel (per-batch-quadrant pipelines) ----------------
__device__ __forceinline__ float sigf(float x) { return 1.0f / (1.0f + __expf(-x)); }
__device__ __forceinline__ float tanhf_fast(float x) {
    float e = __expf(2.0f * x);
    return 1.0f - __fdividef(2.0f, e + 1.0f);
}
__device__ __forceinline__ unsigned ldcg_u32(const void* p) {
    unsigned v;
    asm volatile("ld.global.cg.b32 %0, [%1];" : "=r"(v) : "l"(p));
    return v;
}
__device__ __forceinline__ void spin_until(const unsigned* p, unsigned need) {
    unsigned v;
    do {
        asm volatile("ld.global.acquire.gpu.b32 %0, [%1];" : "=r"(v) : "l"(p));
    } while (v < need);
}

// MMA over N chunks starting at global chunk gc0, with depth-2 prefetch (3-buffer rotation)
template<int N>
__device__ __forceinline__ void mma_chunks(float (&acc)[4][4], const unsigned* hi,
                                           const uint2* Bsm, int gc0,
                                           int br, int br8, int tg, int lane)
{
    const unsigned* lo = hi + 8192;
    unsigned buf[3][8];
    auto loadA = [&](int j, unsigned* d) {
        const int k2b = ((gc0 + j) & 15) * 8;
        d[0] = ldcg_u32(hi + (k2b + tg) * 64 + br);
        d[1] = ldcg_u32(hi + (k2b + tg) * 64 + br8);
        d[2] = ldcg_u32(hi + (k2b + tg + 4) * 64 + br);
        d[3] = ldcg_u32(hi + (k2b + tg + 4) * 64 + br8);
        d[4] = ldcg_u32(lo + (k2b + tg) * 64 + br);
        d[5] = ldcg_u32(lo + (k2b + tg) * 64 + br8);
        d[6] = ldcg_u32(lo + (k2b + tg + 4) * 64 + br);
        d[7] = ldcg_u32(lo + (k2b + tg + 4) * 64 + br8);
    };
    loadA(0, buf[0]);
    if (N > 1) loadA(1, buf[1]);
#pragma unroll
    for (int j = 0; j < N; j++) {
        if (j + 2 < N) loadA(j + 2, buf[(j + 2) % 3]);
        const unsigned* a = buf[j % 3];
        const uint2* bsc = Bsm + (gc0 + j) * 256;
#pragma unroll
        for (int ni = 0; ni < 4; ni++) {
            uint2 bh = bsc[ni * 32 + lane];
            uint2 bl = bsc[128 + ni * 32 + lane];
            mma_bf16(acc[ni][0], acc[ni][1], acc[ni][2], acc[ni][3],
                     a[0], a[1], a[2], a[3], bh.x, bh.y);
            mma_bf16(acc[ni][0], acc[ni][1], acc[ni][2], acc[ni][3],
                     a[0], a[1], a[2], a[3], bl.x, bl.y);
            mma_bf16(acc[ni][0], acc[ni][1], acc[ni][2], acc[ni][3],
                     a[4], a[5], a[6], a[7], bh.x, bh.y);
        }
    }
}

__global__ void __launch_bounds__(NTHR_L) lstm_kernel(float* __restrict__ out)
{
    extern __shared__ uint2 Bs[];             // 64 KB: [chunk][split][ni][lane]
    __shared__ float red[4][4][32][16];       // 32 KB: per-(group, wq) partials
    __shared__ volatile int s_own[4], s_bel[4];  // per-quadrant readiness flags

    const int tid = threadIdx.x;
    const int cta = blockIdx.x;
    const int w = tid >> 5, lane = tid & 31;
    const int wq = w & 3, grp = w >> 2;       // batch-quadrant, K-split group (0..3)
    const int r = lane >> 2, tg = lane & 3;
    const int l = cta / 32, cb = cta % 32;
    const int br  = wq * 16 + r;
    const int br8 = br + 8;

    {
        const uint4* src = (const uint4*)g_B + (size_t)cta * 4096;
        uint4* dst = (uint4*)Bs;
        for (int i = tid; i < 4096; i += NTHR_L) dst[i] = src[i];
    }
    if (tid < 4) { s_own[tid] = -1; s_bel[tid] = -1; }
    __syncthreads();

    float cst[2] = {0.0f, 0.0f};              // epilogue warps keep 2 gate-quads of c

    unsigned* const qOwn = g_qw + (l * 4 + wq) * 32;
    const unsigned* const qBel = g_qw + ((l - 1) * 4 + wq) * 32;
    const unsigned* const qAbo = g_qw + ((l + 1) * 4 + wq) * 32;

    // own-h chunk split 3/3/5/5; below-h 8/8 on grps 2,3
    const int own_gc0 = (grp == 0) ? 0 : (grp == 1) ? 3 : (grp == 2) ? 6 : 11;

    for (int t = 0; t < T_STEPS; t++) {
        const unsigned* ownHi = g_hb + (size_t)(l * 1001 + t) * 16384;   // h_l(t-1)

        float acc[4][4];
#pragma unroll
        for (int ni = 0; ni < 4; ni++)
#pragma unroll
            for (int e = 0; e < 4; e++) acc[ni][e] = 0.0f;

        if (grp < 2) {
            const int nbase = grp * 2;        // epilogue gate-quads {nbase, nbase+1}
            // P prefetch for this half (before any waits)
            float pv[2][4];
            {
                const float* basep = g_P + (size_t)(t * 3 + l) * 1024 * 64;
#pragma unroll
                for (int jj = 0; jj < 2; jj++) {
                    int ni = nbase + jj;
                    int ug = cb * 8 + 2 * ni + (tg >> 1);
                    int oc0 = (tg & 1) * 512 + ug;
                    int oc1 = oc0 + 256;
                    pv[jj][0] = __ldcs(basep + (size_t)oc0 * 64 + br);
                    pv[jj][1] = __ldcs(basep + (size_t)oc1 * 64 + br);
                    pv[jj][2] = __ldcs(basep + (size_t)oc0 * 64 + br8);
                    pv[jj][3] = __ldcs(basep + (size_t)oc1 * 64 + br8);
                }
            }
            if (grp == 0) {
                // quadrant-local readiness poll + L2-residency throttle
                if (lane == 0) {
                    if (l < 2 && t >= 64 && (t & 7) == 0)
                        spin_until(qAbo, 64u * ((unsigned)(t - 64) & ~7u));
                    if (t > 0) spin_until(qOwn, 64u * (unsigned)t);
                }
                __syncwarp();
                if (lane == 0) s_own[wq] = t;
            } else {
                while (s_own[wq] < t) { }
            }
            // 3 own-h chunks on the critical path
            mma_chunks<3>(acc, ownHi, Bs, own_gc0, br, br8, tg, lane);
#pragma unroll
            for (int ni = 0; ni < 4; ni++) {
                float* rd = &red[grp][wq][lane][ni * 4];
                rd[0] = acc[ni][0]; rd[1] = acc[ni][1]; rd[2] = acc[ni][2]; rd[3] = acc[ni][3];
            }
            NBAR(1 + wq);

            // epilogue for this half
            unsigned* whh = g_hb + (size_t)(l * 1001 + t + 1) * 16384;
            unsigned* wll = whh + 8192;
#pragma unroll
            for (int jj = 0; jj < 2; jj++) {
                int ni = nbase + jj;
                float v0 = acc[ni][0], v1 = acc[ni][1], v2 = acc[ni][2], v3 = acc[ni][3];
#pragma unroll
                for (int g = 0; g < 4; g++) {
                    if (g == grp) continue;
                    const float* rd = &red[g][wq][lane][ni * 4];
                    v0 += rd[0]; v1 += rd[1]; v2 += rd[2]; v3 += rd[3];
                }
                v0 += pv[jj][0]; v1 += pv[jj][1]; v2 += pv[jj][2]; v3 += pv[jj][3];
                float s0 = __shfl_xor_sync(0xffffffffu, (tg & 1) ? v0 : v2, 1);
                float s1 = __shfl_xor_sync(0xffffffffu, (tg & 1) ? v1 : v3, 1);
                float gi_, gj_, gf_, go_;
                int brow;
                if (!(tg & 1)) { gi_ = v0; gj_ = v1; gf_ = s0; go_ = s1; brow = br; }
                else           { gi_ = s0; gj_ = s1; gf_ = v2; go_ = v3; brow = br8; }
                float cn = sigf(gf_) * cst[jj] + sigf(gi_) * tanhf_fast(gj_);
                cst[jj] = cn;
                float h = sigf(go_) * tanhf_fast(cn);
                unsigned hh16 = (unsigned)__bfloat16_as_ushort(__float2bfloat16(h));
                float hhf = __bfloat162float(__float2bfloat16(h));
                unsigned hl16 = (unsigned)__bfloat16_as_ushort(__float2bfloat16(h - hhf));
                unsigned ph = __shfl_xor_sync(0xffffffffu, hh16, 2);
                unsigned pl = __shfl_xor_sync(0xffffffffu, hl16, 2);
                if (tg < 2) {
                    int k2 = cb * 4 + ni;
                    whh[k2 * 64 + brow] = hh16 | (ph << 16);
                    wll[k2 * 64 + brow] = hl16 | (pl << 16);
                }
                if (t == T_STEPS - 1) {
                    int ug = cb * 8 + 2 * ni + (tg >> 1);
                    out[brow * 1536 + l * 512 + ug] = cn;
                    out[brow * 1536 + l * 512 + 256 + ug] = h;
                }
            }
            // warp-autonomous release: 2 arrivals per CTA per quadrant (grp0 + grp1)
            __threadfence();
            if (lane == 0) atomicAdd(qOwn, 1u);
        } else {
            // grps 2,3: below-h chunks first (producer runs ahead), then own-h
            if (l > 0) {
                if (grp == 2) {
                    if (lane == 0) spin_until(qBel, 64u * (unsigned)(t + 1));
                    __syncwarp();
                    if (lane == 0) s_bel[wq] = t;
                } else {
                    while (s_bel[wq] < t) { }
                }
                const unsigned* belHi = g_hb + (size_t)((l - 1) * 1001 + t + 1) * 16384;
                mma_chunks<8>(acc, belHi, Bs, 16 + (grp - 2) * 8, br, br8, tg, lane);
            }
            while (s_own[wq] < t) { }
            mma_chunks<5>(acc, ownHi, Bs, own_gc0, br, br8, tg, lane);
#pragma unroll
            for (int ni = 0; ni < 4; ni++) {
                float* rd = &red[grp][wq][lane][ni * 4];
                rd[0] = acc[ni][0]; rd[1] = acc[ni][1]; rd[2] = acc[ni][2]; rd[3] = acc[ni][3];
            }
            NBAR(1 + wq);
        }
    }
}

// ---------------- launch ----------------
extern "C" void kernel_launch(void* const* d_in, const int* in_sizes, int n_in,
                              void* d_out, int out_size) {
    const int*   ids = (const int*)d_in[0];
    const float* emb = (const float*)d_in[1];
    const float* W0x = (const float*)d_in[2];
    const float* W0h = (const float*)d_in[3];
    const float* b0  = (const float*)d_in[4];
    const float* W1x = (const float*)d_in[5];
    const float* W1h = (const float*)d_in[6];
    const float* b1  = (const float*)d_in[7];
    const float* W2x = (const float*)d_in[8];
    const float* W2h = (const float*)d_in[9];
    const float* b2  = (const float*)d_in[10];
    float* out = (float*)d_out;

    static bool attr_set = false;
    if (!attr_set) {
        cudaFuncSetAttribute(lstm_kernel, cudaFuncAttributeMaxDynamicSharedMemorySize, 65536);
        attr_set = true;
    }

    gather_kernel<<<64000, 64>>>(ids, emb);
    wsplit_kernel<<<3072, 256>>>(W0x, W1x, W2x);
    bprep_kernel<<<3072, 256>>>(W0h, W1h, W2h, W1x, W2x);
    dim3 gg(500, 48);
    mma_gemm_kernel<<<gg, 256>>>(b0, b1, b2);
    lstm_kernel<<<NCTA_L, NTHR_L, 65536>>>(out);
}

// round 15
// speedup vs baseline: 1.5367x; 1.1560x over previous
#include <cuda_runtime.h>
#include <cuda_bf16.h>
#include <cstdint>

// Problem constants
#define T_STEPS 1000
#define NCTA_L 96      // persistent grid for LSTM (96 = 3 layers x 32 col-blocks)
#define NTHR_L 512     // 16 warps: 4 K-split groups x 4 batch-quadrant warps

#define NBAR(id) asm volatile("bar.sync %0, %1;" :: "r"(id), "r"(128) : "memory")

// ---------------- device scratch (allocation-free) ----------------
__device__ __nv_bfloat16 g_Xh[(size_t)64000 * 256];   // gathered embeddings, bf16 hi
__device__ __nv_bfloat16 g_Xl[(size_t)64000 * 256];   // bf16 lo residual
__device__ __nv_bfloat16 g_Wh[256 * 3072];            // concat Wx top rows, bf16 hi
__device__ __nv_bfloat16 g_Wl[256 * 3072];            // bf16 lo residual
__device__ float g_P[(size_t)64000 * 3072];           // precomputed x@Wx+b, layout [t][col][b]
__device__ uint2 g_B[NCTA_L * 8192];                  // pre-packed recurrent B fragments (6.3MB)
// Full-history h (bf16, hi plane only): slot(l,t) = l*1001 + t + 1 (t=-1 zero slot).
// Each slot: 128 k2 x 64 b u32 (bf16x2 pairs) = 8192 u32 (32KB).
__device__ unsigned g_hb[(size_t)3 * 1001 * 8192];
__device__ unsigned g_qw[3 * 4 * 32];                 // per-(layer, batch-quadrant) counters

// ---------------- gather + bf16 split ----------------
__global__ void gather_kernel(const int* __restrict__ ids, const float* __restrict__ emb) {
    int r = blockIdx.x;           // r = t*64 + b
    int t = r >> 6, b = r & 63;
    int id = ids[b * 1000 + t];
    float4 v = ((const float4*)(emb + (size_t)id * 256))[threadIdx.x];
    __nv_bfloat16 hx = __float2bfloat16(v.x), hy = __float2bfloat16(v.y);
    __nv_bfloat16 hz = __float2bfloat16(v.z), hw = __float2bfloat16(v.w);
    __nv_bfloat16 lx = __float2bfloat16(v.x - __bfloat162float(hx));
    __nv_bfloat16 ly = __float2bfloat16(v.y - __bfloat162float(hy));
    __nv_bfloat16 lz = __float2bfloat16(v.z - __bfloat162float(hz));
    __nv_bfloat16 lw = __float2bfloat16(v.w - __bfloat162float(hw));
    size_t o = (size_t)r * 256 + threadIdx.x * 4;
    __nv_bfloat162* dh = (__nv_bfloat162*)(g_Xh + o);
    dh[0] = __nv_bfloat162(hx, hy); dh[1] = __nv_bfloat162(hz, hw);
    __nv_bfloat162* dl = (__nv_bfloat162*)(g_Xl + o);
    dl[0] = __nv_bfloat162(lx, ly); dl[1] = __nv_bfloat162(lz, lw);
}

// ---------------- W split ----------------
__global__ void wsplit_kernel(const float* __restrict__ W0x, const float* __restrict__ W1x,
                              const float* __restrict__ W2x) {
    int idx = blockIdx.x * 256 + threadIdx.x;
    int k = idx / 3072, c = idx % 3072;
    int l = c >> 10, cc = c & 1023;
    const float* W = (l == 0) ? W0x : ((l == 1) ? W1x : W2x);
    float v = W[(size_t)k * 1024 + cc];
    __nv_bfloat16 h = __float2bfloat16(v);
    g_Wh[idx] = h;
    g_Wl[idx] = __float2bfloat16(v - __bfloat162float(h));
}

// ---------------- pre-pack recurrent weights + reset counters + zero h(-1) ----------------
__global__ void bprep_kernel(
    const float* __restrict__ W0h, const float* __restrict__ W1h, const float* __restrict__ W2h,
    const float* __restrict__ W1x, const float* __restrict__ W2x)
{
    int gidx = blockIdx.x * 256 + threadIdx.x;
    if (gidx < 3 * 4 * 32) g_qw[gidx] = 0u;
    if (gidx < 3 * 8192) {
        int l = gidx / 8192, i = gidx % 8192;
        g_hb[(size_t)l * 1001 * 8192 + i] = 0u;    // slot(l, -1) = zeros
    }

    int cta = gidx >> 13, rem = gidx & 8191;
    int chunk = rem >> 8, split = (rem >> 7) & 1, ni = (rem >> 5) & 3, lane = rem & 31;
    int l = cta / 32, cb = cta % 32;
    int n = lane >> 2, tg = lane & 3;
    int c = ni * 8 + n;
    int oc = (c & 3) * 256 + cb * 8 + (c >> 2);
    int k0 = chunk * 16;

    uint2 out_v = make_uint2(0u, 0u);
    if (!(l == 0 && chunk >= 16)) {
        const float* Whl = (l == 0) ? W0h : ((l == 1) ? W1h : W2h);
        const float* Wxl = (l <= 1) ? W1x : W2x;
        int offs[4] = {2 * tg, 2 * tg + 1, 2 * tg + 8, 2 * tg + 9};
        unsigned short sv[4];
#pragma unroll
        for (int j = 0; j < 4; j++) {
            int k = k0 + offs[j];
            float v = (k < 256) ? Whl[(size_t)k * 1024 + oc] : Wxl[(size_t)k * 1024 + oc];
            __nv_bfloat16 h = __float2bfloat16(v);
            __nv_bfloat16 lo = __float2bfloat16(v - __bfloat162float(h));
            __nv_bfloat16 sel = split ? lo : h;
            sv[j] = __bfloat16_as_ushort(sel);
        }
        out_v.x = (unsigned)sv[0] | ((unsigned)sv[1] << 16);
        out_v.y = (unsigned)sv[2] | ((unsigned)sv[3] << 16);
    }
    g_B[gidx] = out_v;
}

// ---------------- MMA primitive ----------------
__device__ __forceinline__ void mma_bf16(float& d0, float& d1, float& d2, float& d3,
                                         unsigned a0, unsigned a1, unsigned a2, unsigned a3,
                                         unsigned b0, unsigned b1) {
    asm volatile(
        "mma.sync.aligned.m16n8k16.row.col.f32.bf16.bf16.f32 "
        "{%0,%1,%2,%3},{%4,%5,%6,%7},{%8,%9},{%0,%1,%2,%3};"
        : "+f"(d0), "+f"(d1), "+f"(d2), "+f"(d3)
        : "r"(a0), "r"(a1), "r"(a2), "r"(a3), "r"(b0), "r"(b1));
}

#define LDU(arr, elem_idx) (*(const unsigned*)&(arr)[(elem_idx)])

// ---------------- bf16-split MMA GEMM: P = X @ W + bias (R10-proven version) ----------------
__global__ void __launch_bounds__(256) mma_gemm_kernel(
    const float* __restrict__ b0_, const float* __restrict__ b1_, const float* __restrict__ b2_)
{
    __shared__ __align__(16) __nv_bfloat16 Xh_s[128 * 20];
    __shared__ __align__(16) __nv_bfloat16 Xl_s[128 * 20];
    __shared__ __align__(16) __nv_bfloat16 Wh_s[64 * 20];
    __shared__ __align__(16) __nv_bfloat16 Wl_s[64 * 20];

    const int tid = threadIdx.x;
    const int warp = tid >> 5, lane = tid & 31;
    const int wm = (warp >> 1) * 32, wn = (warp & 1) * 32;
    const int rbase = blockIdx.x * 128;
    const int cbase = blockIdx.y * 64;
    const int layer = cbase >> 10;
    const float* bias = (layer == 0) ? b0_ : ((layer == 1) ? b1_ : b2_);
    const int r = lane >> 2, tg = lane & 3;
    const int xrow = tid >> 1, xhalf = tid & 1;

    float acc[2][4][4];
#pragma unroll
    for (int i = 0; i < 2; i++)
#pragma unroll
        for (int j = 0; j < 4; j++)
#pragma unroll
            for (int e = 0; e < 4; e++) acc[i][j][e] = 0.0f;

    for (int k0 = 0; k0 < 256; k0 += 16) {
        uint4 vh = *(const uint4*)(g_Xh + (size_t)(rbase + xrow) * 256 + k0 + xhalf * 8);
        uint4 vl = *(const uint4*)(g_Xl + (size_t)(rbase + xrow) * 256 + k0 + xhalf * 8);
        __nv_bfloat16 wrh[4], wrl[4];
#pragma unroll
        for (int j = 0; j < 4; j++) {
            int i = tid + j * 256;
            int kk = i >> 6, cc = i & 63;
            wrh[j] = g_Wh[(size_t)(k0 + kk) * 3072 + cbase + cc];
            wrl[j] = g_Wl[(size_t)(k0 + kk) * 3072 + cbase + cc];
        }
        __syncthreads();
        {
            unsigned* dx = (unsigned*)Xh_s + xrow * 10 + xhalf * 4;
            dx[0] = vh.x; dx[1] = vh.y; dx[2] = vh.z; dx[3] = vh.w;
            unsigned* dl = (unsigned*)Xl_s + xrow * 10 + xhalf * 4;
            dl[0] = vl.x; dl[1] = vl.y; dl[2] = vl.z; dl[3] = vl.w;
        }
#pragma unroll
        for (int j = 0; j < 4; j++) {
            int i = tid + j * 256;
            int kk = i >> 6, cc = i & 63;
            Wh_s[cc * 20 + kk] = wrh[j];
            Wl_s[cc * 20 + kk] = wrl[j];
        }
        __syncthreads();

        unsigned ah[2][4], al[2][4];
#pragma unroll
        for (int mi = 0; mi < 2; mi++) {
            int row0 = (wm + mi * 16 + r) * 20;
            int row1 = row0 + 8 * 20;
            ah[mi][0] = LDU(Xh_s, row0 + 2 * tg);
            ah[mi][1] = LDU(Xh_s, row1 + 2 * tg);
            ah[mi][2] = LDU(Xh_s, row0 + 2 * tg + 8);
            ah[mi][3] = LDU(Xh_s, row1 + 2 * tg + 8);
            al[mi][0] = LDU(Xl_s, row0 + 2 * tg);
            al[mi][1] = LDU(Xl_s, row1 + 2 * tg);
            al[mi][2] = LDU(Xl_s, row0 + 2 * tg + 8);
            al[mi][3] = LDU(Xl_s, row1 + 2 * tg + 8);
        }
#pragma unroll
        for (int ni = 0; ni < 4; ni++) {
            int col = (wn + ni * 8 + r) * 20;
            unsigned bh0 = LDU(Wh_s, col + 2 * tg);
            unsigned bh1 = LDU(Wh_s, col + 2 * tg + 8);
            unsigned bl0 = LDU(Wl_s, col + 2 * tg);
            unsigned bl1 = LDU(Wl_s, col + 2 * tg + 8);
#pragma unroll
            for (int mi = 0; mi < 2; mi++) {
                mma_bf16(acc[mi][ni][0], acc[mi][ni][1], acc[mi][ni][2], acc[mi][ni][3],
                         ah[mi][0], ah[mi][1], ah[mi][2], ah[mi][3], bh0, bh1);
                mma_bf16(acc[mi][ni][0], acc[mi][ni][1], acc[mi][ni][2], acc[mi][ni][3],
                         ah[mi][0], ah[mi][1], ah[mi][2], ah[mi][3], bl0, bl1);
                mma_bf16(acc[mi][ni][0], acc[mi][ni][1], acc[mi][ni][2], acc[mi][ni][3],
                         al[mi][0], al[mi][1], al[mi][2], al[mi][3], bh0, bh1);
            }
        }
    }

#pragma unroll
    for (int mi = 0; mi < 2; mi++) {
#pragma unroll
        for (int ni = 0; ni < 4; ni++) {
            int gc = cbase + wn + ni * 8 + 2 * tg;
            float bi0 = bias[gc & 1023];
            float bi1 = bias[(gc + 1) & 1023];
            int grow0 = rbase + wm + mi * 16 + r;
            int grow1 = grow0 + 8;
            size_t o0 = ((size_t)(grow0 >> 6) * 3072 + gc) * 64 + (grow0 & 63);
            size_t o1 = ((size_t)(grow1 >> 6) * 3072 + gc) * 64 + (grow1 & 63);
            g_P[o0]      = acc[mi][ni][0] + bi0;
            g_P[o0 + 64] = acc[mi][ni][1] + bi1;
            g_P[o1]      = acc[mi][ni][2] + bi0;
            g_P[o1 + 64] = acc[mi][ni][3] + bi1;
        }
    }
}

// ---------------- recurrent persistent kernel (per-quadrant pipelines, bf16 h) ----------------
__device__ __forceinline__ float sigf(float x) { return 1.0f / (1.0f + __expf(-x)); }
__device__ __forceinline__ float tanhf_fast(float x) {
    float e = __expf(2.0f * x);
    return 1.0f - __fdividef(2.0f, e + 1.0f);
}
__device__ __forceinline__ unsigned ldcg_u32(const void* p) {
    unsigned v;
    asm volatile("ld.global.cg.b32 %0, [%1];" : "=r"(v) : "l"(p));
    return v;
}
__device__ __forceinline__ void spin_until(const unsigned* p, unsigned need) {
    unsigned v;
    do {
        asm volatile("ld.global.acquire.gpu.b32 %0, [%1];" : "=r"(v) : "l"(p));
    } while (v < need);
}
__device__ __forceinline__ void red_release_add(unsigned* p, unsigned v) {
    asm volatile("red.release.gpu.global.add.u32 [%0], %1;" :: "l"(p), "r"(v) : "memory");
}

// MMA over N chunks starting at global chunk gc0 (B-frag index = h chunk index here),
// hi-plane h only: 4 loads + 8 MMAs per chunk, depth-2 prefetch (3-buffer rotation).
template<int N>
__device__ __forceinline__ void mma_chunks(float (&acc)[4][4], const unsigned* hi,
                                           const uint2* Bsm, int hc0, int gb0,
                                           int br, int br8, int tg, int lane)
{
    unsigned buf[3][4];
    auto loadA = [&](int j, unsigned* d) {
        const int k2b = ((hc0 + j) & 15) * 8;
        d[0] = ldcg_u32(hi + (k2b + tg) * 64 + br);
        d[1] = ldcg_u32(hi + (k2b + tg) * 64 + br8);
        d[2] = ldcg_u32(hi + (k2b + tg + 4) * 64 + br);
        d[3] = ldcg_u32(hi + (k2b + tg + 4) * 64 + br8);
    };
    loadA(0, buf[0]);
    if (N > 1) loadA(1, buf[1]);
#pragma unroll
    for (int j = 0; j < N; j++) {
        if (j + 2 < N) loadA(j + 2, buf[(j + 2) % 3]);
        const unsigned* a = buf[j % 3];
        const uint2* bsc = Bsm + (gb0 + j) * 256;
#pragma unroll
        for (int ni = 0; ni < 4; ni++) {
            uint2 bh = bsc[ni * 32 + lane];
            uint2 bl = bsc[128 + ni * 32 + lane];
            mma_bf16(acc[ni][0], acc[ni][1], acc[ni][2], acc[ni][3],
                     a[0], a[1], a[2], a[3], bh.x, bh.y);
            mma_bf16(acc[ni][0], acc[ni][1], acc[ni][2], acc[ni][3],
                     a[0], a[1], a[2], a[3], bl.x, bl.y);
        }
    }
}

__global__ void __launch_bounds__(NTHR_L) lstm_kernel(float* __restrict__ out)
{
    extern __shared__ uint2 Bs[];             // 64 KB: [chunk][split][ni][lane]
    __shared__ float red[4][4][32][16];       // 32 KB: per-(group, wq) partials
    __shared__ volatile int s_own[4], s_bel[4];  // per-quadrant readiness flags

    const int tid = threadIdx.x;
    const int cta = blockIdx.x;
    const int w = tid >> 5, lane = tid & 31;
    const int wq = w & 3, grp = w >> 2;       // batch-quadrant, K-split group (0..3)
    const int r = lane >> 2, tg = lane & 3;
    const int l = cta / 32, cb = cta % 32;
    const int br  = wq * 16 + r;
    const int br8 = br + 8;

    {
        const uint4* src = (const uint4*)g_B + (size_t)cta * 4096;
        uint4* dst = (uint4*)Bs;
        for (int i = tid; i < 4096; i += NTHR_L) dst[i] = src[i];
    }
    if (tid < 4) { s_own[tid] = -1; s_bel[tid] = -1; }
    __syncthreads();

    float cst[2] = {0.0f, 0.0f};              // epilogue warps keep 2 gate-quads of c

    unsigned* const qOwn = g_qw + (l * 4 + wq) * 32;
    const unsigned* const qBel = g_qw + ((l - 1) * 4 + wq) * 32;
    const unsigned* const qAbo = g_qw + ((l + 1) * 4 + wq) * 32;

    // own-h chunk split 4/4/4/4; below-h 8/8 on grps 2,3
    const int own_gc0 = grp * 4;

    for (int t = 0; t < T_STEPS; t++) {
        const unsigned* ownHi = g_hb + (size_t)(l * 1001 + t) * 8192;   // h_l(t-1)

        float acc[4][4];
#pragma unroll
        for (int ni = 0; ni < 4; ni++)
#pragma unroll
            for (int e = 0; e < 4; e++) acc[ni][e] = 0.0f;

        if (grp < 2) {
            const int nbase = grp * 2;        // epilogue gate-quads {nbase, nbase+1}
            // P prefetch for this half (before any waits)
            float pv[2][4];
            {
                const float* basep = g_P + (size_t)(t * 3 + l) * 1024 * 64;
#pragma unroll
                for (int jj = 0; jj < 2; jj++) {
                    int ni = nbase + jj;
                    int ug = cb * 8 + 2 * ni + (tg >> 1);
                    int oc0 = (tg & 1) * 512 + ug;
                    int oc1 = oc0 + 256;
                    pv[jj][0] = __ldcs(basep + (size_t)oc0 * 64 + br);
                    pv[jj][1] = __ldcs(basep + (size_t)oc1 * 64 + br);
                    pv[jj][2] = __ldcs(basep + (size_t)oc0 * 64 + br8);
                    pv[jj][3] = __ldcs(basep + (size_t)oc1 * 64 + br8);
                }
            }
            if (grp == 0) {
                // quadrant-local readiness poll + L2-residency throttle
                if (lane == 0) {
                    if (l < 2 && t >= 64 && (t & 7) == 0)
                        spin_until(qAbo, 64u * ((unsigned)(t - 64) & ~7u));
                    if (t > 0) spin_until(qOwn, 64u * (unsigned)t);
                }
                __syncwarp();
                if (lane == 0) s_own[wq] = t;
            } else {
                while (s_own[wq] < t) { }
            }
            // 4 own-h chunks on the critical path
            mma_chunks<4>(acc, ownHi, Bs, own_gc0, own_gc0, br, br8, tg, lane);
#pragma unroll
            for (int ni = 0; ni < 4; ni++) {
                float* rd = &red[grp][wq][lane][ni * 4];
                rd[0] = acc[ni][0]; rd[1] = acc[ni][1]; rd[2] = acc[ni][2]; rd[3] = acc[ni][3];
            }
            NBAR(1 + wq);

            // epilogue for this half
            unsigned* whh = g_hb + (size_t)(l * 1001 + t + 1) * 8192;
#pragma unroll
            for (int jj = 0; jj < 2; jj++) {
                int ni = nbase + jj;
                float v0 = acc[ni][0], v1 = acc[ni][1], v2 = acc[ni][2], v3 = acc[ni][3];
#pragma unroll
                for (int g = 0; g < 4; g++) {
                    if (g == grp) continue;
                    const float* rd = &red[g][wq][lane][ni * 4];
                    v0 += rd[0]; v1 += rd[1]; v2 += rd[2]; v3 += rd[3];
                }
                v0 += pv[jj][0]; v1 += pv[jj][1]; v2 += pv[jj][2]; v3 += pv[jj][3];
                float s0 = __shfl_xor_sync(0xffffffffu, (tg & 1) ? v0 : v2, 1);
                float s1 = __shfl_xor_sync(0xffffffffu, (tg & 1) ? v1 : v3, 1);
                float gi_, gj_, gf_, go_;
                int brow;
                if (!(tg & 1)) { gi_ = v0; gj_ = v1; gf_ = s0; go_ = s1; brow = br; }
                else           { gi_ = s0; gj_ = s1; gf_ = v2; go_ = v3; brow = br8; }
                float cn = sigf(gf_) * cst[jj] + sigf(gi_) * tanhf_fast(gj_);
                cst[jj] = cn;
                float h = sigf(go_) * tanhf_fast(cn);
                unsigned hh16 = (unsigned)__bfloat16_as_ushort(__float2bfloat16(h));
                unsigned ph = __shfl_xor_sync(0xffffffffu, hh16, 2);
                if (tg < 2) {
                    int k2 = cb * 4 + ni;
                    whh[k2 * 64 + brow] = hh16 | (ph << 16);
                }
                if (t == T_STEPS - 1) {
                    int ug = cb * 8 + 2 * ni + (tg >> 1);
                    out[brow * 1536 + l * 512 + ug] = cn;
                    out[brow * 1536 + l * 512 + 256 + ug] = h;
                }
            }
            // release: fire-and-forget reduction with release semantics
            if (lane == 0) red_release_add(qOwn, 1u);
        } else {
            // grps 2,3: below-h chunks first (producer runs ahead), then own-h
            if (l > 0) {
                if (grp == 2) {
                    if (lane == 0) spin_until(qBel, 64u * (unsigned)(t + 1));
                    __syncwarp();
                    if (lane == 0) s_bel[wq] = t;
                } else {
                    while (s_bel[wq] < t) { }
                }
                const unsigned* belHi = g_hb + (size_t)((l - 1) * 1001 + t + 1) * 8192;
                mma_chunks<8>(acc, belHi, Bs, (grp - 2) * 8, 16 + (grp - 2) * 8,
                              br, br8, tg, lane);
            }
            while (s_own[wq] < t) { }
            mma_chunks<4>(acc, ownHi, Bs, own_gc0, own_gc0, br, br8, tg, lane);
#pragma unroll
            for (int ni = 0; ni < 4; ni++) {
                float* rd = &red[grp][wq][lane][ni * 4];
                rd[0] = acc[ni][0]; rd[1] = acc[ni][1]; rd[2] = acc[ni][2]; rd[3] = acc[ni][3];
            }
            NBAR(1 + wq);
        }
    }
}

// ---------------- launch ----------------
extern "C" void kernel_launch(void* const* d_in, const int* in_sizes, int n_in,
                              void* d_out, int out_size) {
    const int*   ids = (const int*)d_in[0];
    const float* emb = (const float*)d_in[1];
    const float* W0x = (const float*)d_in[2];
    const float* W0h = (const float*)d_in[3];
    const float* b0  = (const float*)d_in[4];
    const float* W1x = (const float*)d_in[5];
    const float* W1h = (const float*)d_in[6];
    const float* b1  = (const float*)d_in[7];
    const float* W2x = (const float*)d_in[8];
    const float* W2h = (const float*)d_in[9];
    const float* b2  = (const float*)d_in[10];
    float* out = (float*)d_out;

    static bool attr_set = false;
    if (!attr_set) {
        cudaFuncSetAttribute(lstm_kernel, cudaFuncAttributeMaxDynamicSharedMemorySize, 65536);
        attr_set = true;
    }

    gather_kernel<<<64000, 64>>>(ids, emb);
    wsplit_kernel<<<3072, 256>>>(W0x, W1x, W2x);
    bprep_kernel<<<3072, 256>>>(W0h, W1h, W2h, W1x, W2x);
    dim3 gg(500, 48);
    mma_gemm_kernel<<<gg, 256>>>(b0, b1, b2);
    lstm_kernel<<<NCTA_L, NTHR_L, 65536>>>(out);
}